// round 12
// baseline (speedup 1.0000x reference)
#include <cuda_runtime.h>
#include <cstdint>

// CoCoNet_72249939853425 (GB300 / sm_103a)
//
// Steady-state replay period is bounded by DRAM *write drain* of the 155 MB
// output (~5.3 TB/s measured, invariant to all SM-side knobs). Trick:
// between graph replays the output is re-written in place, so dirty L2
// lines that stay resident never need a DRAM writeback. ROIs [0,108) of
// both planes (108 MB < 126 MB L2) are stored with
// st.global.L2::evict_last.v8.b32 (sm_103 requires 256-bit stores for
// evict_last); the 40 MB tail streams out with .cs (evict-first) so it
// never displaces the resident set.
#define NUM_ROI 148
#define QQ      5
#define NN      131072

#define TPB        64
#define N_PER_THR  8     // 32 B per plane per ROI -> v8.b32 stores

#define RESIDENT   108   // ROIs [0,108) pinned: 108 * 2 * 0.5 MB = 108 MB

__device__ __forceinline__ void st_evict_last8(float* p, const float* v) {
    asm volatile(
        "st.global.L2::evict_last.v8.b32 [%0], {%1,%2,%3,%4,%5,%6,%7,%8};"
        :: "l"(p), "f"(v[0]), "f"(v[1]), "f"(v[2]), "f"(v[3]),
           "f"(v[4]), "f"(v[5]), "f"(v[6]), "f"(v[7])
        : "memory");
}

__global__ __launch_bounds__(TPB) void coconet_kernel(
    const float* __restrict__ X,    // [N, 1]
    const float* __restrict__ Z,    // [N, 5]
    const float* __restrict__ Wr,   // [148, 5]
    const float* __restrict__ br,   // [148]
    const float* __restrict__ Wf,   // [148, 6]
    const float* __restrict__ bf,   // [148]
    float* __restrict__ out)        // [2, 148, N] : r_out then f_out
{
    // Packed per-ROI weights: 4 x float4 per ROI
    //  w0 = {Wf0, Wf1, Wf2, Wf3}
    //  w1 = {Wf4, Wf5, bf,  br }
    //  w2 = {Wr0, Wr1, Wr2, Wr3}
    //  w3 = {Wr4, 0,   0,   0  }
    __shared__ float4 wsh[NUM_ROI][4];

    const int tid = threadIdx.x;

    for (int i = tid; i < NUM_ROI; i += TPB) {
        const float* wf = Wf + i * 6;
        const float* wr = Wr + i * 5;
        wsh[i][0] = make_float4(wf[0], wf[1], wf[2], wf[3]);
        wsh[i][1] = make_float4(wf[4], wf[5], bf[i], br[i]);
        wsh[i][2] = make_float4(wr[0], wr[1], wr[2], wr[3]);
        wsh[i][3] = make_float4(wr[4], 0.f, 0.f, 0.f);
    }
    __syncthreads();

    const int n0 = (blockIdx.x * TPB + tid) * N_PER_THR;

    // Vectorized input loads: X[n0..n0+7] = 2 float4; Z rows n0..n0+7 are
    // 40 contiguous floats starting at Z + 5*n0 (16B-aligned: n0 % 8 == 0)
    // = 10 float4 loads.
    float x[N_PER_THR];
    {
        const float4 xv0 = __ldg(reinterpret_cast<const float4*>(X + n0));
        const float4 xv1 = __ldg(reinterpret_cast<const float4*>(X + n0 + 4));
        x[0] = xv0.x; x[1] = xv0.y; x[2] = xv0.z; x[3] = xv0.w;
        x[4] = xv1.x; x[5] = xv1.y; x[6] = xv1.z; x[7] = xv1.w;
    }

    float zb[N_PER_THR * QQ];
    {
        const float4* zp4 = reinterpret_cast<const float4*>(Z + (size_t)n0 * QQ);
#pragma unroll
        for (int i = 0; i < 10; ++i) {
            const float4 v = __ldg(zp4 + i);
            zb[4 * i + 0] = v.x;
            zb[4 * i + 1] = v.y;
            zb[4 * i + 2] = v.z;
            zb[4 * i + 3] = v.w;
        }
    }
    // z[j][q] == zb[5*j + q]

    float* __restrict__ out_r = out;
    float* __restrict__ out_f = out + (size_t)NUM_ROI * NN;

#pragma unroll 1
    for (int r = 0; r < NUM_ROI; ++r) {
        const float4 a = wsh[r][0];
        const float4 b = wsh[r][1];
        const float4 c = wsh[r][2];
        const float4 d = wsh[r][3];

        float rv[N_PER_THR], fv[N_PER_THR];
#pragma unroll
        for (int j = 0; j < N_PER_THR; ++j) {
            const float z0 = zb[5 * j + 0];
            const float z1 = zb[5 * j + 1];
            const float z2 = zb[5 * j + 2];
            const float z3 = zb[5 * j + 3];
            const float z4 = zb[5 * j + 4];
            // f_out = bf + Wf[0]*X + Wf[1..5] . Z
            float f = b.z;
            f = fmaf(a.x, x[j], f);
            f = fmaf(a.y, z0, f);
            f = fmaf(a.z, z1, f);
            f = fmaf(a.w, z2, f);
            f = fmaf(b.x, z3, f);
            f = fmaf(b.y, z4, f);
            fv[j] = f;
            // r_out = br + Wr . Z
            float rr = b.w;
            rr = fmaf(c.x, z0, rr);
            rr = fmaf(c.y, z1, rr);
            rr = fmaf(c.z, z2, rr);
            rr = fmaf(c.w, z3, rr);
            rr = fmaf(d.x, z4, rr);
            rv[j] = rr;
        }

        const size_t off = (size_t)r * NN + n0;
        if (r < RESIDENT) {
            // L2-resident portion: re-dirtied in place each replay, no DRAM
            // writeback in steady state.
            st_evict_last8(out_r + off, rv);
            st_evict_last8(out_f + off, fv);
        } else {
            // Streaming tail: evict-first so it never displaces the resident set.
            __stcs(reinterpret_cast<float4*>(out_r + off),
                   make_float4(rv[0], rv[1], rv[2], rv[3]));
            __stcs(reinterpret_cast<float4*>(out_r + off + 4),
                   make_float4(rv[4], rv[5], rv[6], rv[7]));
            __stcs(reinterpret_cast<float4*>(out_f + off),
                   make_float4(fv[0], fv[1], fv[2], fv[3]));
            __stcs(reinterpret_cast<float4*>(out_f + off + 4),
                   make_float4(fv[4], fv[5], fv[6], fv[7]));
        }
    }
}

extern "C" void kernel_launch(void* const* d_in, const int* in_sizes, int n_in,
                              void* d_out, int out_size)
{
    const float* X  = (const float*)d_in[0];
    const float* Z  = (const float*)d_in[1];
    const float* Wr = (const float*)d_in[2];
    const float* br = (const float*)d_in[3];
    const float* Wf = (const float*)d_in[4];
    const float* bf = (const float*)d_in[5];
    float* out = (float*)d_out;

    const int grid = NN / (TPB * N_PER_THR);  // 256
    coconet_kernel<<<grid, TPB>>>(X, Z, Wr, br, Wf, bf, out);
}

// round 13
// speedup vs baseline: 1.0156x; 1.0156x over previous
#include <cuda_runtime.h>
#include <cstdint>

// FINAL KERNEL — CoCoNet_72249939853425 (GB300 / sm_103a)
//
// 148 per-ROI GEMVs (K=5 and K=6) over N=131072 rows; output [2,148,N] fp32
// = 155 MB. The kernel is DRAM-write-drain bound: steady-state graph-replay
// period = 155 MB / ~5.31 TB/s pure-write bandwidth ~= 29.2 us, invariant
// to occupancy (11-40%), write-stream count (512-2048), burst length
// (2-8 KB), store width (64/128/256b), and cache policy (.cs/.wb/.wt/
// L2::evict_last) — all swept and falsified over 12 rounds. .cs wins the
// policy comparison because it spreads the writeback drain evenly through
// the kernel instead of bunching it into a tail that collides with the
// next replay.
//
// Config (best measured, twice: 29.18 / 29.22 us): 256 CTAs x 128 threads,
// 4 consecutive n per thread, single-pass vectorized inputs (6x LDG.128 per
// thread), smem-packed weights (4x float4 broadcast per ROI), __stcs float4
// stores.
#define NUM_ROI 148
#define QQ      5
#define NN      131072

#define TPB        128
#define N_PER_THR  4

__global__ __launch_bounds__(TPB) void coconet_kernel(
    const float* __restrict__ X,    // [N, 1]
    const float* __restrict__ Z,    // [N, 5]
    const float* __restrict__ Wr,   // [148, 5]
    const float* __restrict__ br,   // [148]
    const float* __restrict__ Wf,   // [148, 6]
    const float* __restrict__ bf,   // [148]
    float* __restrict__ out)        // [2, 148, N] : r_out then f_out
{
    // Packed per-ROI weights: 4 x float4 per ROI
    //  w0 = {Wf0, Wf1, Wf2, Wf3}
    //  w1 = {Wf4, Wf5, bf,  br }
    //  w2 = {Wr0, Wr1, Wr2, Wr3}
    //  w3 = {Wr4, 0,   0,   0  }
    __shared__ float4 wsh[NUM_ROI][4];

    const int tid = threadIdx.x;

    for (int i = tid; i < NUM_ROI; i += TPB) {
        const float* wf = Wf + i * 6;
        const float* wr = Wr + i * 5;
        wsh[i][0] = make_float4(wf[0], wf[1], wf[2], wf[3]);
        wsh[i][1] = make_float4(wf[4], wf[5], bf[i], br[i]);
        wsh[i][2] = make_float4(wr[0], wr[1], wr[2], wr[3]);
        wsh[i][3] = make_float4(wr[4], 0.f, 0.f, 0.f);
    }
    __syncthreads();

    const int n0 = (blockIdx.x * TPB + tid) * N_PER_THR;

    // Vectorized input loads: X[n0..n0+3] = 1 float4; Z rows n0..n0+3 are
    // 20 contiguous floats starting at Z + 5*n0 (16B-aligned since n0 % 4 == 0)
    // = 5 float4 loads.
    const float4 xv = __ldg(reinterpret_cast<const float4*>(X + n0));
    const float x[N_PER_THR] = {xv.x, xv.y, xv.z, xv.w};

    float zb[N_PER_THR * QQ];
    {
        const float4* zp4 = reinterpret_cast<const float4*>(Z + (size_t)n0 * QQ);
#pragma unroll
        for (int i = 0; i < 5; ++i) {
            const float4 v = __ldg(zp4 + i);
            zb[4 * i + 0] = v.x;
            zb[4 * i + 1] = v.y;
            zb[4 * i + 2] = v.z;
            zb[4 * i + 3] = v.w;
        }
    }
    // z[j][q] == zb[5*j + q]

    float* __restrict__ out_r = out;
    float* __restrict__ out_f = out + (size_t)NUM_ROI * NN;

#pragma unroll 2
    for (int r = 0; r < NUM_ROI; ++r) {
        const float4 a = wsh[r][0];
        const float4 b = wsh[r][1];
        const float4 c = wsh[r][2];
        const float4 d = wsh[r][3];

        float rv[N_PER_THR], fv[N_PER_THR];
#pragma unroll
        for (int j = 0; j < N_PER_THR; ++j) {
            const float z0 = zb[5 * j + 0];
            const float z1 = zb[5 * j + 1];
            const float z2 = zb[5 * j + 2];
            const float z3 = zb[5 * j + 3];
            const float z4 = zb[5 * j + 4];
            // f_out = bf + Wf[0]*X + Wf[1..5] . Z
            float f = b.z;
            f = fmaf(a.x, x[j], f);
            f = fmaf(a.y, z0, f);
            f = fmaf(a.z, z1, f);
            f = fmaf(a.w, z2, f);
            f = fmaf(b.x, z3, f);
            f = fmaf(b.y, z4, f);
            fv[j] = f;
            // r_out = br + Wr . Z
            float rr = b.w;
            rr = fmaf(c.x, z0, rr);
            rr = fmaf(c.y, z1, rr);
            rr = fmaf(c.z, z2, rr);
            rr = fmaf(c.w, z3, rr);
            rr = fmaf(d.x, z4, rr);
            rv[j] = rr;
        }

        const size_t off = (size_t)r * NN + n0;
        __stcs(reinterpret_cast<float4*>(out_r + off),
               make_float4(rv[0], rv[1], rv[2], rv[3]));
        __stcs(reinterpret_cast<float4*>(out_f + off),
               make_float4(fv[0], fv[1], fv[2], fv[3]));
    }
}

extern "C" void kernel_launch(void* const* d_in, const int* in_sizes, int n_in,
                              void* d_out, int out_size)
{
    const float* X  = (const float*)d_in[0];
    const float* Z  = (const float*)d_in[1];
    const float* Wr = (const float*)d_in[2];
    const float* br = (const float*)d_in[3];
    const float* Wf = (const float*)d_in[4];
    const float* bf = (const float*)d_in[5];
    float* out = (float*)d_out;

    const int grid = NN / (TPB * N_PER_THR);  // 256
    coconet_kernel<<<grid, TPB>>>(X, Z, Wr, br, Wf, bf, out);
}

// round 14
// speedup vs baseline: 1.0361x; 1.0202x over previous
#include <cuda_runtime.h>
#include <cstdint>

// CoCoNet_72249939853425 (GB300 / sm_103a)
//
// DRAM-write-drain bound: replay period ~= 155 MB / ~5.3 TB/s. This round's
// single change: per-block ROI rotation (block b starts at ROI (b*59)%148)
// so the chip's instantaneous write footprint spans the whole 155 MB output
// instead of one ~1 MB ROI slice -> more DRAM banks/channels active
// concurrently during the write drain.
//
// Base config (best measured): 256 CTAs x 128 threads, 4 consecutive n per
// thread, vectorized inputs (6x LDG.128), smem-packed weights, __stcs
// float4 stores.
#define NUM_ROI 148
#define QQ      5
#define NN      131072

#define TPB        128
#define N_PER_THR  4
#define ROT_STEP   59   // coprime with 148 -> full-period block decorrelation

__global__ __launch_bounds__(TPB) void coconet_kernel(
    const float* __restrict__ X,    // [N, 1]
    const float* __restrict__ Z,    // [N, 5]
    const float* __restrict__ Wr,   // [148, 5]
    const float* __restrict__ br,   // [148]
    const float* __restrict__ Wf,   // [148, 6]
    const float* __restrict__ bf,   // [148]
    float* __restrict__ out)        // [2, 148, N] : r_out then f_out
{
    // Packed per-ROI weights: 4 x float4 per ROI
    //  w0 = {Wf0, Wf1, Wf2, Wf3}
    //  w1 = {Wf4, Wf5, bf,  br }
    //  w2 = {Wr0, Wr1, Wr2, Wr3}
    //  w3 = {Wr4, 0,   0,   0  }
    __shared__ float4 wsh[NUM_ROI][4];

    const int tid = threadIdx.x;

    for (int i = tid; i < NUM_ROI; i += TPB) {
        const float* wf = Wf + i * 6;
        const float* wr = Wr + i * 5;
        wsh[i][0] = make_float4(wf[0], wf[1], wf[2], wf[3]);
        wsh[i][1] = make_float4(wf[4], wf[5], bf[i], br[i]);
        wsh[i][2] = make_float4(wr[0], wr[1], wr[2], wr[3]);
        wsh[i][3] = make_float4(wr[4], 0.f, 0.f, 0.f);
    }
    __syncthreads();

    const int n0 = (blockIdx.x * TPB + tid) * N_PER_THR;

    // Vectorized input loads: X[n0..n0+3] = 1 float4; Z rows n0..n0+3 are
    // 20 contiguous floats starting at Z + 5*n0 (16B-aligned since n0 % 4 == 0)
    // = 5 float4 loads.
    const float4 xv = __ldg(reinterpret_cast<const float4*>(X + n0));
    const float x[N_PER_THR] = {xv.x, xv.y, xv.z, xv.w};

    float zb[N_PER_THR * QQ];
    {
        const float4* zp4 = reinterpret_cast<const float4*>(Z + (size_t)n0 * QQ);
#pragma unroll
        for (int i = 0; i < 5; ++i) {
            const float4 v = __ldg(zp4 + i);
            zb[4 * i + 0] = v.x;
            zb[4 * i + 1] = v.y;
            zb[4 * i + 2] = v.z;
            zb[4 * i + 3] = v.w;
        }
    }
    // z[j][q] == zb[5*j + q]

    float* __restrict__ out_r = out;
    float* __restrict__ out_f = out + (size_t)NUM_ROI * NN;

    // Per-block ROI rotation: decorrelate write addresses across blocks.
    int r = (int)((blockIdx.x * (unsigned)ROT_STEP) % NUM_ROI);

#pragma unroll 2
    for (int i = 0; i < NUM_ROI; ++i) {
        const float4 a = wsh[r][0];
        const float4 b = wsh[r][1];
        const float4 c = wsh[r][2];
        const float4 d = wsh[r][3];

        float rv[N_PER_THR], fv[N_PER_THR];
#pragma unroll
        for (int j = 0; j < N_PER_THR; ++j) {
            const float z0 = zb[5 * j + 0];
            const float z1 = zb[5 * j + 1];
            const float z2 = zb[5 * j + 2];
            const float z3 = zb[5 * j + 3];
            const float z4 = zb[5 * j + 4];
            // f_out = bf + Wf[0]*X + Wf[1..5] . Z
            float f = b.z;
            f = fmaf(a.x, x[j], f);
            f = fmaf(a.y, z0, f);
            f = fmaf(a.z, z1, f);
            f = fmaf(a.w, z2, f);
            f = fmaf(b.x, z3, f);
            f = fmaf(b.y, z4, f);
            fv[j] = f;
            // r_out = br + Wr . Z
            float rr = b.w;
            rr = fmaf(c.x, z0, rr);
            rr = fmaf(c.y, z1, rr);
            rr = fmaf(c.z, z2, rr);
            rr = fmaf(c.w, z3, rr);
            rr = fmaf(d.x, z4, rr);
            rv[j] = rr;
        }

        const size_t off = (size_t)r * NN + n0;
        __stcs(reinterpret_cast<float4*>(out_r + off),
               make_float4(rv[0], rv[1], rv[2], rv[3]));
        __stcs(reinterpret_cast<float4*>(out_f + off),
               make_float4(fv[0], fv[1], fv[2], fv[3]));

        r += 1;
        if (r == NUM_ROI) r = 0;
    }
}

extern "C" void kernel_launch(void* const* d_in, const int* in_sizes, int n_in,
                              void* d_out, int out_size)
{
    const float* X  = (const float*)d_in[0];
    const float* Z  = (const float*)d_in[1];
    const float* Wr = (const float*)d_in[2];
    const float* br = (const float*)d_in[3];
    const float* Wf = (const float*)d_in[4];
    const float* bf = (const float*)d_in[5];
    float* out = (float*)d_out;

    const int grid = NN / (TPB * N_PER_THR);  // 256
    coconet_kernel<<<grid, TPB>>>(X, Z, Wr, br, Wf, bf, out);
}

// round 15
// speedup vs baseline: 1.0383x; 1.0021x over previous
#include <cuda_runtime.h>
#include <cstdint>

// FINAL KERNEL — CoCoNet_72249939853425 (GB300 / sm_103a)
//
// 148 per-ROI GEMVs (K=5 and K=6) over N=131072 rows; output [2,148,N] fp32
// = 155 MB. DRAM-write-drain bound: steady-state graph-replay period
// = 155 MB / ~5.3 TB/s pure-write bandwidth ≈ 29.2-30.2 us (±0.8 us run
// noise). Swept and falsified over 14 rounds: occupancy (5.5-40%), CTA
// shape (32-512 thr), store width (64/128/256b), cache policy
// (.cs/.wb/.wt/L2::evict_last), load vectorization, wave balance,
// write-stream count, burst length, ROI-order rotation. .cs + in-order
// contiguous sweep is the measured optimum: it spreads the writeback drain
// evenly through the kernel and keeps the controller-friendly sequential
// address pattern.
//
// Config (best measured, twice: 29.18 / 29.22 us): 256 CTAs x 128 threads,
// 4 consecutive n per thread, single-pass vectorized inputs (6x LDG.128 per
// thread), smem-packed weights (4x float4 broadcast per ROI), __stcs float4
// stores.
#define NUM_ROI 148
#define QQ      5
#define NN      131072

#define TPB        128
#define N_PER_THR  4

__global__ __launch_bounds__(TPB) void coconet_kernel(
    const float* __restrict__ X,    // [N, 1]
    const float* __restrict__ Z,    // [N, 5]
    const float* __restrict__ Wr,   // [148, 5]
    const float* __restrict__ br,   // [148]
    const float* __restrict__ Wf,   // [148, 6]
    const float* __restrict__ bf,   // [148]
    float* __restrict__ out)        // [2, 148, N] : r_out then f_out
{
    // Packed per-ROI weights: 4 x float4 per ROI
    //  w0 = {Wf0, Wf1, Wf2, Wf3}
    //  w1 = {Wf4, Wf5, bf,  br }
    //  w2 = {Wr0, Wr1, Wr2, Wr3}
    //  w3 = {Wr4, 0,   0,   0  }
    __shared__ float4 wsh[NUM_ROI][4];

    const int tid = threadIdx.x;

    for (int i = tid; i < NUM_ROI; i += TPB) {
        const float* wf = Wf + i * 6;
        const float* wr = Wr + i * 5;
        wsh[i][0] = make_float4(wf[0], wf[1], wf[2], wf[3]);
        wsh[i][1] = make_float4(wf[4], wf[5], bf[i], br[i]);
        wsh[i][2] = make_float4(wr[0], wr[1], wr[2], wr[3]);
        wsh[i][3] = make_float4(wr[4], 0.f, 0.f, 0.f);
    }
    __syncthreads();

    const int n0 = (blockIdx.x * TPB + tid) * N_PER_THR;

    // Vectorized input loads: X[n0..n0+3] = 1 float4; Z rows n0..n0+3 are
    // 20 contiguous floats starting at Z + 5*n0 (16B-aligned since n0 % 4 == 0)
    // = 5 float4 loads.
    const float4 xv = __ldg(reinterpret_cast<const float4*>(X + n0));
    const float x[N_PER_THR] = {xv.x, xv.y, xv.z, xv.w};

    float zb[N_PER_THR * QQ];
    {
        const float4* zp4 = reinterpret_cast<const float4*>(Z + (size_t)n0 * QQ);
#pragma unroll
        for (int i = 0; i < 5; ++i) {
            const float4 v = __ldg(zp4 + i);
            zb[4 * i + 0] = v.x;
            zb[4 * i + 1] = v.y;
            zb[4 * i + 2] = v.z;
            zb[4 * i + 3] = v.w;
        }
    }
    // z[j][q] == zb[5*j + q]

    float* __restrict__ out_r = out;
    float* __restrict__ out_f = out + (size_t)NUM_ROI * NN;

#pragma unroll 2
    for (int r = 0; r < NUM_ROI; ++r) {
        const float4 a = wsh[r][0];
        const float4 b = wsh[r][1];
        const float4 c = wsh[r][2];
        const float4 d = wsh[r][3];

        float rv[N_PER_THR], fv[N_PER_THR];
#pragma unroll
        for (int j = 0; j < N_PER_THR; ++j) {
            const float z0 = zb[5 * j + 0];
            const float z1 = zb[5 * j + 1];
            const float z2 = zb[5 * j + 2];
            const float z3 = zb[5 * j + 3];
            const float z4 = zb[5 * j + 4];
            // f_out = bf + Wf[0]*X + Wf[1..5] . Z
            float f = b.z;
            f = fmaf(a.x, x[j], f);
            f = fmaf(a.y, z0, f);
            f = fmaf(a.z, z1, f);
            f = fmaf(a.w, z2, f);
            f = fmaf(b.x, z3, f);
            f = fmaf(b.y, z4, f);
            fv[j] = f;
            // r_out = br + Wr . Z
            float rr = b.w;
            rr = fmaf(c.x, z0, rr);
            rr = fmaf(c.y, z1, rr);
            rr = fmaf(c.z, z2, rr);
            rr = fmaf(c.w, z3, rr);
            rr = fmaf(d.x, z4, rr);
            rv[j] = rr;
        }

        const size_t off = (size_t)r * NN + n0;
        __stcs(reinterpret_cast<float4*>(out_r + off),
               make_float4(rv[0], rv[1], rv[2], rv[3]));
        __stcs(reinterpret_cast<float4*>(out_f + off),
               make_float4(fv[0], fv[1], fv[2], fv[3]));
    }
}

extern "C" void kernel_launch(void* const* d_in, const int* in_sizes, int n_in,
                              void* d_out, int out_size)
{
    const float* X  = (const float*)d_in[0];
    const float* Z  = (const float*)d_in[1];
    const float* Wr = (const float*)d_in[2];
    const float* br = (const float*)d_in[3];
    const float* Wf = (const float*)d_in[4];
    const float* bf = (const float*)d_in[5];
    float* out = (float*)d_out;

    const int grid = NN / (TPB * N_PER_THR);  // 256
    coconet_kernel<<<grid, TPB>>>(X, Z, Wr, br, Wf, bf, out);
}